// round 4
// baseline (speedup 1.0000x reference)
#include <cuda_runtime.h>
#include <cuda_bf16.h>
#include <cstddef>

// Problem constants
#define Bn 4
#define Hn 256
#define Wn 256
#define Cn 16
#define TH 4          // tile height (pixels per block, y)
#define TW 8          // tile width  (pixels per block, x)
#define HALO 3        // max k=7 -> pad 3
#define SH (TH + 2 * HALO)   // 10
#define SW (TW + 2 * HALO)   // 14
#define NTHREADS (TH * TW * Cn)  // 512

__device__ __forceinline__ void ce(float& a, float& b) {
    float lo = fminf(a, b);
    float hi = fmaxf(a, b);
    a = lo;
    b = hi;
}

// Batcher odd-even mergesort for arbitrary N (ascending), fully unrolled,
// register-resident. Comparators with index >= N dropped (== +inf padding).
// Single-rank extraction lets ptxas DCE prune the comparator cone.
template <int N>
__device__ __forceinline__ void oe_sort(float* a) {
#pragma unroll
    for (int p = 1; p < N; p <<= 1) {
#pragma unroll
        for (int k = p; k >= 1; k >>= 1) {
#pragma unroll
            for (int j = k % p; j + k < N; j += 2 * k) {
#pragma unroll
                for (int i = 0; i < k; i++) {
                    if (i + j + k < N) {
                        if ((i + j) / (2 * p) == (i + j + k) / (2 * p)) {
                            ce(a[i + j], a[i + j + k]);
                        }
                    }
                }
            }
        }
    }
}

__global__ void __launch_bounds__(NTHREADS, 1)
adaptive_mblock_kernel(const float* __restrict__ x,
                       const float* __restrict__ hk,
                       float* __restrict__ out) {
    __shared__ float s_x[SH][SW][Cn];          // input tile with halo (~8.75 KB)
    __shared__ float s_feat[TH][TW][48];       // [m7 | m3 | m5] per pixel (6 KB)
    __shared__ float s_w[48 * Cn];             // 1x1 conv weights [48][16] (3 KB)

    const int c  = threadIdx.x;   // channel 0..15
    const int tw = threadIdx.y;   // 0..TW-1
    const int th = threadIdx.z;   // 0..TH-1
    const int tid = (th * TW + tw) * Cn + c;

    const int w0 = blockIdx.x * TW;
    const int h0 = blockIdx.y * TH;
    const int b  = blockIdx.z;

    // ---- load 1x1 conv weights (768 floats) ----
#pragma unroll
    for (int i = tid; i < 48 * Cn; i += NTHREADS) {
        s_w[i] = hk[i];
    }

    // ---- load input tile with zero-padded halo ----
    const float* xb = x + (size_t)b * Hn * Wn * Cn;
    for (int idx = tid; idx < SH * SW * Cn; idx += NTHREADS) {
        int cc = idx & (Cn - 1);
        int p  = idx >> 4;           // Cn == 16
        int ww = p % SW;
        int hh = p / SW;
        int gh = h0 + hh - HALO;
        int gw = w0 + ww - HALO;
        float v = 0.0f;
        if (gh >= 0 && gh < Hn && gw >= 0 && gw < Wn) {
            v = xb[((size_t)gh * Wn + gw) * Cn + cc];
        }
        s_x[hh][ww][cc] = v;
    }
    __syncthreads();

    // ---- rank selections (smallest window first keeps peak regs low) ----
    // 3x3: n=9,  m=n/2-1=3,  ascending index n-m = 6
    float m3;
    {
        float v[9];
#pragma unroll
        for (int r = 0; r < 3; r++)
#pragma unroll
            for (int q = 0; q < 3; q++)
                v[r * 3 + q] = s_x[th + 2 + r][tw + 2 + q][c];
        oe_sort<9>(v);
        m3 = v[6];
    }

    // 5x5: n=25, m=11, ascending index 14
    float m5;
    {
        float v[25];
#pragma unroll
        for (int r = 0; r < 5; r++)
#pragma unroll
            for (int q = 0; q < 5; q++)
                v[r * 5 + q] = s_x[th + 1 + r][tw + 1 + q][c];
        oe_sort<25>(v);
        m5 = v[14];
    }

    // 7x7: n=49, m=23, ascending index 26
    float m7;
    {
        float v[49];
#pragma unroll
        for (int r = 0; r < 7; r++)
#pragma unroll
            for (int q = 0; q < 7; q++)
                v[r * 7 + q] = s_x[th + r][tw + q][c];
        oe_sort<49>(v);
        m7 = v[26];
    }

    // feat layout matches reference concat: [m7, m3, m5]
    s_feat[th][tw][c]          = m7;
    s_feat[th][tw][Cn + c]     = m3;
    s_feat[th][tw][2 * Cn + c] = m5;
    __syncthreads();

    // ---- 1x1 conv: out[o] = sum_i feat[i] * w[i][o], o = c ----
    float acc = 0.0f;
#pragma unroll
    for (int i = 0; i < 48; i++) {
        acc = fmaf(s_feat[th][tw][i], s_w[i * Cn + c], acc);
    }
    out[(((size_t)(b * Hn + h0 + th)) * Wn + (w0 + tw)) * Cn + c] = acc;
}

extern "C" void kernel_launch(void* const* d_in, const int* in_sizes, int n_in,
                              void* d_out, int out_size) {
    (void)in_sizes; (void)n_in; (void)out_size;
    const float* x  = (const float*)d_in[0];
    const float* hk = (const float*)d_in[1];
    float* out = (float*)d_out;

    dim3 block(Cn, TW, TH);                 // (16, 8, 4) = 512
    dim3 grid(Wn / TW, Hn / TH, Bn);        // (32, 64, 4)
    adaptive_mblock_kernel<<<grid, block>>>(x, hk, out);
}

// round 9
// speedup vs baseline: 5.4705x; 5.4705x over previous
#include <cuda_runtime.h>
#include <cuda_bf16.h>
#include <cstddef>

// Problem constants
#define Bn 4
#define Hn 256
#define Wn 256
#define Cn 16
#define TH 4          // tile height (pixels per block, y)
#define TW 8          // tile width  (pixels per block, x)
#define HALO 3        // max k=7 -> pad 3
#define SH (TH + 2 * HALO)   // 10
#define SW (TW + 2 * HALO)   // 14
#define NTHREADS (TH * TW * Cn)  // 512

// Upper bound on Batcher comparator count for N <= 49 (full n=64 net is 543).
#define MAXC 560

// Compile-time Batcher odd-even mergesort comparator table for size N.
// Same generation rule (and thus the same comparator sequence) as the
// R4-validated oe_sort (rel_err == 0.0) — correctness preserved by construction.
template <int N>
struct Net {
    int lo[MAXC];
    int hi[MAXC];
    int cnt;
    constexpr Net() : lo{}, hi{}, cnt(0) {
        for (int p = 1; p < N; p <<= 1)
            for (int k = p; k >= 1; k >>= 1)
                for (int j = k % p; j + k < N; j += 2 * k)
                    for (int i = 0; i < k; i++)
                        if (i + j + k < N)
                            if ((i + j) / (2 * p) == (i + j + k) / (2 * p)) {
                                lo[cnt] = i + j;
                                hi[cnt] = i + j + k;
                                cnt++;
                            }
    }
};

template <int N>
struct NetHolder {
    static constexpr Net<N> net{};
};

__device__ __forceinline__ void ce(float& a, float& b) {
    float lo = fminf(a, b);
    float hi = fmaxf(a, b);
    a = lo;
    b = hi;
}

// Apply comparators [Lo, Lo+Len) via BINARY range-split template recursion
// (depth ~log2(MAXC) ~= 10, vs ~400 for a linear chain). In-order traversal
// reproduces the exact linear comparator order. All array indices are
// constant expressions -> guaranteed register promotion, no dynamic indexing.
template <int N, int Lo, int Len>
struct Apply {
    static __device__ __forceinline__ void run(float (&a)[N]) {
        if constexpr (Len == 1) {
            if constexpr (Lo < NetHolder<N>::net.cnt) {
                ce(a[NetHolder<N>::net.lo[Lo]], a[NetHolder<N>::net.hi[Lo]]);
            }
        } else if constexpr (Lo < NetHolder<N>::net.cnt) {
            Apply<N, Lo, Len / 2>::run(a);
            Apply<N, Lo + Len / 2, Len - Len / 2>::run(a);
        }
    }
};

template <int N>
__device__ __forceinline__ void oe_sort(float (&a)[N]) {
    Apply<N, 0, MAXC>::run(a);
}

__global__ void __launch_bounds__(NTHREADS, 1)
adaptive_mblock_kernel(const float* __restrict__ x,
                       const float* __restrict__ hk,
                       float* __restrict__ out) {
    __shared__ float s_x[SH][SW][Cn];          // input tile with halo (~8.75 KB)
    __shared__ float s_feat[TH][TW][48];       // [m7 | m3 | m5] per pixel (6 KB)
    __shared__ float s_w[48 * Cn];             // 1x1 conv weights [48][16] (3 KB)

    const int c  = threadIdx.x;   // channel 0..15
    const int tw = threadIdx.y;   // 0..TW-1
    const int th = threadIdx.z;   // 0..TH-1
    const int tid = (th * TW + tw) * Cn + c;

    const int w0 = blockIdx.x * TW;
    const int h0 = blockIdx.y * TH;
    const int b  = blockIdx.z;

    // ---- load 1x1 conv weights (768 floats) ----
#pragma unroll
    for (int i = tid; i < 48 * Cn; i += NTHREADS) {
        s_w[i] = hk[i];
    }

    // ---- load input tile with zero-padded halo ----
    const float* xb = x + (size_t)b * Hn * Wn * Cn;
    for (int idx = tid; idx < SH * SW * Cn; idx += NTHREADS) {
        int cc = idx & (Cn - 1);
        int p  = idx >> 4;           // Cn == 16
        int ww = p % SW;
        int hh = p / SW;
        int gh = h0 + hh - HALO;
        int gw = w0 + ww - HALO;
        float v = 0.0f;
        if (gh >= 0 && gh < Hn && gw >= 0 && gw < Wn) {
            v = xb[((size_t)gh * Wn + gw) * Cn + cc];
        }
        s_x[hh][ww][cc] = v;
    }
    __syncthreads();

    // ---- rank selections (smallest window first keeps peak regs low) ----
    // 3x3: n=9,  m=n/2-1=3,  ascending index n-m = 6
    float m3;
    {
        float v[9];
#pragma unroll
        for (int r = 0; r < 3; r++)
#pragma unroll
            for (int q = 0; q < 3; q++)
                v[r * 3 + q] = s_x[th + 2 + r][tw + 2 + q][c];
        oe_sort<9>(v);
        m3 = v[6];
    }

    // 5x5: n=25, m=11, ascending index 14
    float m5;
    {
        float v[25];
#pragma unroll
        for (int r = 0; r < 5; r++)
#pragma unroll
            for (int q = 0; q < 5; q++)
                v[r * 5 + q] = s_x[th + 1 + r][tw + 1 + q][c];
        oe_sort<25>(v);
        m5 = v[14];
    }

    // 7x7: n=49, m=23, ascending index 26
    float m7;
    {
        float v[49];
#pragma unroll
        for (int r = 0; r < 7; r++)
#pragma unroll
            for (int q = 0; q < 7; q++)
                v[r * 7 + q] = s_x[th + r][tw + q][c];
        oe_sort<49>(v);
        m7 = v[26];
    }

    // feat layout matches reference concat: [m7, m3, m5]
    s_feat[th][tw][c]          = m7;
    s_feat[th][tw][Cn + c]     = m3;
    s_feat[th][tw][2 * Cn + c] = m5;
    __syncthreads();

    // ---- 1x1 conv: out[o] = sum_i feat[i] * w[i][o], o = c ----
    float acc = 0.0f;
#pragma unroll
    for (int i = 0; i < 48; i++) {
        acc = fmaf(s_feat[th][tw][i], s_w[i * Cn + c], acc);
    }
    out[(((size_t)(b * Hn + h0 + th)) * Wn + (w0 + tw)) * Cn + c] = acc;
}

extern "C" void kernel_launch(void* const* d_in, const int* in_sizes, int n_in,
                              void* d_out, int out_size) {
    (void)in_sizes; (void)n_in; (void)out_size;
    const float* x  = (const float*)d_in[0];
    const float* hk = (const float*)d_in[1];
    float* out = (float*)d_out;

    dim3 block(Cn, TW, TH);                 // (16, 8, 4) = 512
    dim3 grid(Wn / TW, Hn / TH, Bn);        // (32, 64, 4)
    adaptive_mblock_kernel<<<grid, block>>>(x, hk, out);
}